// round 13
// baseline (speedup 1.0000x reference)
#include <cuda_runtime.h>
#include <cuda_fp16.h>
#include <math.h>

#define B_    2
#define L_    2048
#define D_    1024
#define FFN_  4096
#define NH_   8
#define HD_   128
#define BL_   (B_ * L_)
#define CHUNK_ ((long long)L_ * HD_)
#define LN_EPS 1e-5f
#define RSQRT_HD 0.08838834764831845f

// ---- GEMM tiling ----
#define BM 128
#define BK 32
#define STAGES 4
#define APITCH 40
#define A_PL_B (BM * APITCH * 2)           // 10240 bytes

// ---------------- scratch (device globals: allocation-free) ----------------
__device__ __align__(16) __half g_hh  [BL_ * D_];
__device__ __align__(16) __half g_Wqkv[(size_t)D_ * 3 * D_];
__device__ __align__(16) __half g_Woh [D_ * D_];
__device__ __align__(16) __half g_W1h [(size_t)D_ * FFN_];
__device__ __align__(16) __half g_W2h [(size_t)FFN_ * D_];
__device__ __align__(16) __half g_qh  [BL_ * D_];
__device__ __align__(16) __half g_kh  [BL_ * D_];
__device__ __align__(16) __half g_vh  [BL_ * D_];
__device__ __align__(16) __half g_ch  [BL_ * D_];
__device__ __align__(16) __half g_h1h [BL_ * D_];
__device__ __align__(16) __half g_fh  [(size_t)BL_ * FFN_];
__device__ __align__(16) __half g_Ph  [(size_t)B_ * NH_ * L_ * L_];
__device__ float g_S  [(size_t)B_ * NH_ * L_ * L_];
__device__ float g_hsa[BL_ * D_];
__device__ float g_h1 [BL_ * D_];
__device__ float g_hf [BL_ * D_];
__device__ float g_rq [BL_ * 4];
__device__ float g_rk [BL_ * 4];

// ---------------- asm helpers ----------------
#define LDSM4(R, addr) asm volatile( \
    "ldmatrix.sync.aligned.m8n8.x4.shared.b16 {%0,%1,%2,%3}, [%4];" \
    : "=r"((R)[0]), "=r"((R)[1]), "=r"((R)[2]), "=r"((R)[3]) : "r"(addr))

#define LDSM4T(R, addr) asm volatile( \
    "ldmatrix.sync.aligned.m8n8.x4.trans.shared.b16 {%0,%1,%2,%3}, [%4];" \
    : "=r"((R)[0]), "=r"((R)[1]), "=r"((R)[2]), "=r"((R)[3]) : "r"(addr))

#define MMA16816(AC, A, B0, B1) asm volatile( \
    "mma.sync.aligned.m16n8k16.row.col.f32.f16.f16.f32 " \
    "{%0,%1,%2,%3},{%4,%5,%6,%7},{%8,%9},{%0,%1,%2,%3};" \
    : "+f"((AC)[0]), "+f"((AC)[1]), "+f"((AC)[2]), "+f"((AC)[3]) \
    : "r"((A)[0]), "r"((A)[1]), "r"((A)[2]), "r"((A)[3]), "r"(B0), "r"(B1))

#define CPA16(dst, src) asm volatile( \
    "cp.async.cg.shared.global [%0], [%1], 16;" :: "r"(dst), "l"(src))

// ---------------- single-term fp16 tensor-core GEMM (templated tile) -------
// C = op(alpha * A@B + bias). A: [M,K] row-major. B: [K,N] row-major.
// nSplit: route 1024-wide output column groups to C0/C1/C2 (fused QKV).
template <int BNT, int MINB>
__global__ __launch_bounds__(256, MINB)
void gemm_f16_t(const __half* __restrict__ Ah, const __half* __restrict__ Bh,
                const float* __restrict__ bias,
                float* __restrict__ Cf, __half* __restrict__ C0,
                __half* __restrict__ C1, __half* __restrict__ C2,
                int K, int lda, int ldb, int ldc,
                long long sA, long long sB, long long sC,
                float alpha, int doBias, int doRelu, int nSplit)
{
    constexpr int BPITCH = BNT + 8;
    constexpr int B_PL_B = BK * BPITCH * 2;
    constexpr int STAGE_B = A_PL_B + B_PL_B;
    constexpr int NI = BNT / 32;
    constexpr int NP = BNT / 64;
    constexpr int WC = BNT / 4;
    constexpr int BCHK = BNT / 8;

    extern __shared__ char smem[];
    const unsigned smemS = (unsigned)__cvta_generic_to_shared(smem);
    const int tid = threadIdx.x, lane = tid & 31, w = tid >> 5;

    const int bz = blockIdx.z;
    int rowTile = blockIdx.y * BM, colTile = blockIdx.x * BNT;
    const __half* pA = Ah + (long long)bz * sA + (long long)rowTile * lda;
    const __half* pB = Bh + (long long)bz * sB + colTile;
    const long long cOff = (long long)bz * sC;

    // fused-QKV routing: pick dest buffer by 1024-block, fold colTile
    __half* Ch = C0;
    if (nSplit) {
        const int sel = colTile >> 10;
        Ch = (sel == 0) ? C0 : (sel == 1) ? C1 : C2;
        colTile &= 1023;
    }

    const int wRow = (w >> 2) * 64, wCol = (w & 3) * WC;
    const int aR0 = tid >> 2, aP0 = tid & 3;
    const int nT = K / BK;

    auto load_stage = [&](int slot, int k0) {
        const unsigned base = smemS + (unsigned)slot * STAGE_B;
#pragma unroll
        for (int i = 0; i < 2; i++) {
            const int ar = aR0 + i * 64;
            CPA16(base + (unsigned)(ar * (APITCH * 2) + aP0 * 16),
                  pA + (long long)ar * lda + k0 + aP0 * 8);
        }
#pragma unroll
        for (int i = 0; i < NP; i++) {
            const int u = tid + i * 256;
            const int br = u / BCHK, bp = u % BCHK;
            CPA16(base + A_PL_B + (unsigned)(br * (BPITCH * 2) + bp * 16),
                  pB + (long long)(k0 + br) * ldb + bp * 8);
        }
        asm volatile("cp.async.commit_group;");
    };

    const int aLR = lane & 15, aLC = (lane >> 4) * 8;
    const int bLR = ((lane >> 3) & 1) * 8 + (lane & 7);
    const int bLC = (lane >> 4) * 8;

    float acc[4][NI][4];
#pragma unroll
    for (int i = 0; i < 4; i++)
#pragma unroll
        for (int j = 0; j < NI; j++)
#pragma unroll
            for (int e = 0; e < 4; e++) acc[i][j][e] = 0.f;

    load_stage(0, 0);
    load_stage(1, (1 < nT ? 1 : nT - 1) * BK);
    load_stage(2, (2 < nT ? 2 : nT - 1) * BK);

    for (int t = 0; t < nT; ++t) {
        asm volatile("cp.async.wait_group 2;" ::: "memory");
        __syncthreads();
        {
            const int s = t + 3;
            load_stage((t + 3) & (STAGES - 1), (s < nT ? s : nT - 1) * BK);
        }
        const unsigned sb = smemS + (unsigned)(t & (STAGES - 1)) * STAGE_B;

        // ---- fragment prefetch: issue ALL ldsm for both kk halves first ----
        unsigned ah[2][4][4], bh[2][NP][4];
#pragma unroll
        for (int kk = 0; kk < 2; kk++) {
#pragma unroll
            for (int mi = 0; mi < 4; mi++) {
                unsigned adr = sb +
                    (unsigned)(((wRow + mi * 16 + aLR) * APITCH + kk * 16 + aLC) << 1);
                LDSM4(ah[kk][mi], adr);
            }
#pragma unroll
            for (int np = 0; np < NP; np++) {
                unsigned adr = sb + A_PL_B +
                    (unsigned)(((kk * 16 + bLR) * BPITCH + wCol + np * 16 + bLC) << 1);
                LDSM4T(bh[kk][np], adr);
            }
        }
#pragma unroll
        for (int kk = 0; kk < 2; kk++)
#pragma unroll
            for (int mi = 0; mi < 4; mi++)
#pragma unroll
                for (int ni = 0; ni < NI; ni++)
                    MMA16816(acc[mi][ni], ah[kk][mi],
                             bh[kk][ni >> 1][(ni & 1) * 2], bh[kk][ni >> 1][(ni & 1) * 2 + 1]);
    }

    // epilogue
#pragma unroll
    for (int mi = 0; mi < 4; mi++)
#pragma unroll
        for (int ni = 0; ni < NI; ni++) {
            const int r0 = rowTile + wRow + mi * 16 + (lane >> 2);
            const int c  = colTile + wCol + ni * 8 + (lane & 3) * 2;
            float* a = acc[mi][ni];
#pragma unroll
            for (int hrow = 0; hrow < 2; hrow++) {
                const int r = r0 + hrow * 8;
                float o0 = alpha * a[hrow * 2 + 0];
                float o1 = alpha * a[hrow * 2 + 1];
                if (doBias) { o0 += bias[c]; o1 += bias[c + 1]; }
                if (doRelu) { o0 = fmaxf(o0, 0.f); o1 = fmaxf(o1, 0.f); }
                const long long idx = cOff + (long long)r * ldc + c;
                if (Cf) {
                    *(float2*)&Cf[idx] = make_float2(o0, o1);
                } else {
                    __half2 p; p.x = __float2half_rn(o0); p.y = __float2half_rn(o1);
                    *(__half2*)&Ch[idx] = p;
                }
            }
        }
}

// ---------------- batched fp32 -> fp16 convert (up to 4 tensors) -----------
// Each dest may have an outer pitch: dst[row * pitch + col], rows of 1024.
__global__ __launch_bounds__(256)
void conv4_kernel(const float* __restrict__ s0, const float* __restrict__ s1,
                  const float* __restrict__ s2, const float* __restrict__ s3,
                  __half* __restrict__ o0, __half* __restrict__ o1,
                  __half* __restrict__ o2, __half* __restrict__ o3,
                  long long n0, long long n1, long long n2, long long n3)
{
    long long i = ((long long)blockIdx.x * 256 + threadIdx.x) * 8;
    const float* s; __half* o;
    if (i < n0)                     { s = s0; o = o0; }
    else if ((i -= n0) < n1)        { s = s1; o = o1; }
    else if ((i -= n1) < n2)        { s = s2; o = o2; }
    else if ((i -= n2) < n3)        { s = s3; o = o3; }
    else return;
    float4 v0 = *(const float4*)(s + i);
    float4 v1 = *(const float4*)(s + i + 4);
    __half2 r[4];
    r[0].x = __float2half_rn(v0.x); r[0].y = __float2half_rn(v0.y);
    r[1].x = __float2half_rn(v0.z); r[1].y = __float2half_rn(v0.w);
    r[2].x = __float2half_rn(v1.x); r[2].y = __float2half_rn(v1.y);
    r[3].x = __float2half_rn(v1.z); r[3].y = __float2half_rn(v1.w);
    *(uint4*)&o[i] = *(uint4*)r;
}

// fp32 [D,D] -> fp16 into packed [D, 3D] buffer at column offset
__global__ __launch_bounds__(256)
void convpack_kernel(const float* __restrict__ s, __half* __restrict__ o,
                     int colOff)
{
    const long long i = ((long long)blockIdx.x * 256 + threadIdx.x) * 8;
    if (i >= (long long)D_ * D_) return;
    const int row = (int)(i >> 10), col = (int)(i & 1023);
    float4 v0 = *(const float4*)(s + i);
    float4 v1 = *(const float4*)(s + i + 4);
    __half2 r[4];
    r[0].x = __float2half_rn(v0.x); r[0].y = __float2half_rn(v0.y);
    r[1].x = __float2half_rn(v0.z); r[1].y = __float2half_rn(v0.w);
    r[2].x = __float2half_rn(v1.x); r[2].y = __float2half_rn(v1.y);
    r[3].x = __float2half_rn(v1.z); r[3].y = __float2half_rn(v1.w);
    *(uint4*)&o[(long long)row * (3 * D_) + colOff + col] = *(uint4*)r;
}

// ---------------- rank-4 relative projections ----------------
__global__ void rproj_kernel(const float* __restrict__ rh,
                             const float* __restrict__ Wrq,
                             const float* __restrict__ Wrk,
                             float* __restrict__ rq, float* __restrict__ rk)
{
    const int i = blockIdx.x * blockDim.x + threadIdx.x;
    if (i >= BL_) return;
    const float h0 = rh[i * 4 + 0], h1v = rh[i * 4 + 1];
    const float h2 = rh[i * 4 + 2], h3 = rh[i * 4 + 3];
#pragma unroll
    for (int r = 0; r < 4; r++) {
        rq[i * 4 + r] = h0 * Wrq[r] + h1v * Wrq[4 + r] + h2 * Wrq[8 + r] + h3 * Wrq[12 + r];
        rk[i * 4 + r] = h0 * Wrk[r] + h1v * Wrk[4 + r] + h2 * Wrk[8 + r] + h3 * Wrk[12 + r];
    }
}

// ---------------- block reduction ----------------
__device__ __forceinline__ float blockReduce(float v, float* red, bool isMax)
{
    __syncthreads();
#pragma unroll
    for (int o = 16; o > 0; o >>= 1) {
        float t = __shfl_xor_sync(0xffffffffu, v, o);
        v = isMax ? fmaxf(v, t) : (v + t);
    }
    const int warp = threadIdx.x >> 5, lane = threadIdx.x & 31;
    if (lane == 0) red[warp] = v;
    __syncthreads();
    if (warp == 0) {
        v = (lane < 8) ? red[lane] : (isMax ? -INFINITY : 0.f);
#pragma unroll
        for (int o = 4; o > 0; o >>= 1) {
            float t = __shfl_xor_sync(0xffffffffu, v, o);
            v = isMax ? fmaxf(v, t) : (v + t);
        }
        if (lane == 0) red[0] = v;
    }
    __syncthreads();
    return red[0];
}

// ---------------- fused rel-bias + softmax -> fp16 ----------------
__global__ __launch_bounds__(256)
void softmax_bias_kernel(const float* __restrict__ S,
                         const float* __restrict__ rq,
                         const float* __restrict__ rk,
                         __half* __restrict__ Ph)
{
    __shared__ float red[32];
    const int l = blockIdx.x, n = blockIdx.y, b = blockIdx.z;
    const long long rowOff = ((((long long)b * NH_ + n) * L_) + l) * L_;
    const float* row = S + rowOff;
    const float* rqp = rq + ((long long)b * L_ + l) * 4;
    const float* rkp = rk + (long long)b * L_ * 4;
    const float q0 = rqp[0] * 0.5f, q1 = rqp[1] * 0.5f;
    const float q2 = rqp[2] * 0.5f, q3 = rqp[3] * 0.5f;
    const int tid = threadIdx.x;

    float vals[8];
    float vmax = -INFINITY;
#pragma unroll
    for (int j = 0; j < 8; j++) {
        const int m = j * 256 + tid;
        const float bias = q0 * rkp[m] + q1 * rkp[L_ + m]
                         + q2 * rkp[2 * L_ + m] + q3 * rkp[3 * L_ + m];
        const float v = row[m] + bias;
        vals[j] = v;
        vmax = fmaxf(vmax, v);
    }
    vmax = blockReduce(vmax, red, true);

    float sum = 0.f;
#pragma unroll
    for (int j = 0; j < 8; j++) {
        vals[j] = __expf(vals[j] - vmax);
        sum += vals[j];
    }
    sum = blockReduce(sum, red, false);
    const float inv = 1.f / sum;
#pragma unroll
    for (int j = 0; j < 8; j++)
        Ph[rowOff + j * 256 + tid] = __float2half_rn(vals[j] * inv);
}

// ---------------- fused residual-add + LayerNorm (+ optional fp16 out) -----
__global__ __launch_bounds__(256)
void add_ln_kernel(const float* __restrict__ x, const float* __restrict__ y,
                   const float* __restrict__ g, const float* __restrict__ be,
                   float* __restrict__ outF, __half* __restrict__ outH)
{
    __shared__ float red[32];
    const long long row = blockIdx.x;
    const float* xp = x + row * D_;
    const float* yp = y + row * D_;
    const int tid = threadIdx.x;

    float v[4];
    float s = 0.f;
#pragma unroll
    for (int j = 0; j < 4; j++) {
        const int i = j * 256 + tid;
        v[j] = xp[i] + yp[i];
        s += v[j];
    }
    const float mean = blockReduce(s, red, false) * (1.f / D_);

    float sq = 0.f;
#pragma unroll
    for (int j = 0; j < 4; j++) {
        const float d = v[j] - mean;
        sq += d * d;
    }
    const float var = blockReduce(sq, red, false) * (1.f / D_);
    const float rstd = rsqrtf(var + LN_EPS);
#pragma unroll
    for (int j = 0; j < 4; j++) {
        const int i = j * 256 + tid;
        const float o = (v[j] - mean) * rstd * g[i] + be[i];
        outF[row * D_ + i] = o;
        if (outH) outH[row * D_ + i] = __float2half_rn(o);
    }
}

// ---------------- host helpers ----------------
#define SMEM_256 (STAGES * (A_PL_B + BK * (256 + 8) * 2))   // 108544
#define SMEM_128 (STAGES * (A_PL_B + BK * (128 + 8) * 2))   // 75776

static void gemm256(const __half* Ah, const __half* Bh,
                    const float* bias, float* Cf, __half* Ch,
                    int M, int N, int K, int lda, int ldb, int ldc,
                    long long sA, long long sB, long long sC, int batch,
                    float alpha, int doBias, int doRelu,
                    __half* C1 = nullptr, __half* C2 = nullptr, int nSplit = 0)
{
    dim3 grid(N / 256, M / BM, batch), block(256);
    gemm_f16_t<256, 1><<<grid, block, SMEM_256>>>(Ah, Bh, bias, Cf, Ch, C1, C2,
                                                  K, lda, ldb, ldc, sA, sB, sC,
                                                  alpha, doBias, doRelu, nSplit);
}

static void gemm128(const __half* Ah, const __half* Bh,
                    const float* bias, float* Cf, __half* Ch,
                    int M, int N, int K, int lda, int ldb, int ldc,
                    long long sA, long long sB, long long sC, int batch,
                    float alpha, int doBias, int doRelu)
{
    dim3 grid(N / 128, M / BM, batch), block(256);
    gemm_f16_t<128, 2><<<grid, block, SMEM_128>>>(Ah, Bh, bias, Cf, Ch, nullptr, nullptr,
                                                  K, lda, ldb, ldc, sA, sB, sC,
                                                  alpha, doBias, doRelu, 0);
}

template <typename T>
static T* sym(T* symbol) { void* p; cudaGetSymbolAddress(&p, (const void*)symbol); return (T*)p; }

extern "C" void kernel_launch(void* const* d_in, const int* in_sizes, int n_in,
                              void* d_out, int out_size)
{
    const float* h   = (const float*)d_in[0];
    const float* rh  = (const float*)d_in[1];
    const float* Wq  = (const float*)d_in[2];
    const float* Wk  = (const float*)d_in[3];
    const float* Wv  = (const float*)d_in[4];
    const float* Wo  = (const float*)d_in[5];
    const float* Wrk = (const float*)d_in[6];
    const float* Wrq = (const float*)d_in[7];
    const float* W1  = (const float*)d_in[8];
    const float* b1  = (const float*)d_in[9];
    const float* W2  = (const float*)d_in[10];
    const float* b2  = (const float*)d_in[11];
    const float* g1  = (const float*)d_in[12];
    const float* be1 = (const float*)d_in[13];
    const float* g2  = (const float*)d_in[14];
    const float* be2 = (const float*)d_in[15];
    float* out = (float*)d_out;

    cudaFuncSetAttribute(gemm_f16_t<256, 1>,
                         cudaFuncAttributeMaxDynamicSharedMemorySize, SMEM_256);
    cudaFuncSetAttribute(gemm_f16_t<128, 2>,
                         cudaFuncAttributeMaxDynamicSharedMemorySize, SMEM_128);

    __half *hh = sym(g_hh), *Wqkv = sym(g_Wqkv);
    __half *Woh = sym(g_Woh), *W1h = sym(g_W1h), *W2h = sym(g_W2h);
    __half *qh = sym(g_qh), *kh = sym(g_kh), *vh = sym(g_vh);
    __half *ch = sym(g_ch), *h1h = sym(g_h1h), *fh = sym(g_fh);
    __half *Ph = sym(g_Ph);
    float *S = sym(g_S), *hsa = sym(g_hsa), *h1 = sym(g_h1), *hf = sym(g_hf);
    float *rq = sym(g_rq), *rk = sym(g_rk);

    const long long nH = (long long)BL_ * D_;      // 4M
    const long long nW = (long long)D_ * D_;       // 1M
    const long long nF = (long long)D_ * FFN_;     // 4M
    const int cgrid = (int)(nW / 2048);

    // 0) converts: h (+ packed QKV weights)
    conv4_kernel<<<(int)(nH / 2048), 256>>>(h, nullptr, nullptr, nullptr,
                                            hh, nullptr, nullptr, nullptr, nH, 0, 0, 0);
    convpack_kernel<<<cgrid, 256>>>(Wq, Wqkv, 0);
    convpack_kernel<<<cgrid, 256>>>(Wk, Wqkv, D_);
    convpack_kernel<<<cgrid, 256>>>(Wv, Wqkv, 2 * D_);
    // 4) fused QKV projection: [4096,1024] @ [1024,3072], split into q/k/v
    gemm256(hh, Wqkv, nullptr, nullptr, qh, BL_, 3 * D_, D_, D_, 3 * D_, D_,
            0, 0, 0, 1, 1.f, 0, 0, kh, vh, 1);
    // 5) scores: per (b,head), S = Q[2048x128] @ Kt[128x2048] / sqrt(HD)
    gemm256(qh, kh, nullptr, S, nullptr, L_, L_, HD_, HD_, L_, L_,
            CHUNK_, CHUNK_, (long long)L_ * L_, B_ * NH_, RSQRT_HD, 0, 0);
    // 6) rank-4 projections
    rproj_kernel<<<BL_ / 256, 256>>>(rh, Wrq, Wrk, rq, rk);
    // 7) convert Wo, W1, W2
    conv4_kernel<<<(int)((nW + 2 * nF) / 2048), 256>>>(
        Wo, W1, W2, nullptr, Woh, W1h, W2h, nullptr, nW, nF, nF, 0);
    // 8) fused rel-bias + softmax -> P fp16
    {
        dim3 grid(L_, NH_, B_);
        softmax_bias_kernel<<<grid, 256>>>(S, rq, rk, Ph);
    }
    // 9) context: P[2048x2048] @ V[2048x128]
    gemm128(Ph, vh, nullptr, nullptr, ch, L_, HD_, L_, L_, HD_, HD_,
            (long long)L_ * L_, CHUNK_, CHUNK_, B_ * NH_, 1.f, 0, 0);
    // 10) output projection
    gemm256(ch, Woh, nullptr, hsa, nullptr, BL_, D_, D_, D_, D_, D_, 0, 0, 0, 1, 1.f, 0, 0);
    // 11) h1 = LN(hsa + h)
    add_ln_kernel<<<BL_, 256>>>(hsa, h, g1, be1, h1, h1h);
    // 12) FFN up: relu(h1 @ W1 + b1)
    gemm256(h1h, W1h, b1, nullptr, fh, BL_, FFN_, D_, D_, FFN_, FFN_, 0, 0, 0, 1, 1.f, 1, 1);
    // 13) FFN down: ffn @ W2 + b2
    gemm256(fh, W2h, b2, hf, nullptr, BL_, D_, FFN_, FFN_, D_, D_, 0, 0, 0, 1, 1.f, 1, 0);
    // 14) h2 = LN(h1 + hf) -> out
    add_ln_kernel<<<BL_, 256>>>(h1, hf, g2, be2, out, nullptr);
}

// round 14
// speedup vs baseline: 1.0647x; 1.0647x over previous
#include <cuda_runtime.h>
#include <cuda_fp16.h>
#include <math.h>

#define B_    2
#define L_    2048
#define D_    1024
#define FFN_  4096
#define NH_   8
#define HD_   128
#define BL_   (B_ * L_)
#define CHUNK_ ((long long)L_ * HD_)
#define LN_EPS 1e-5f
#define RSQRT_HD 0.08838834764831845f

#define BK 64
#define STAGES 3
#define APITCH (BK + 8)                    // 72 halfs per A smem row

// ---------------- scratch (device globals: allocation-free) ----------------
__device__ __align__(16) __half g_hh  [BL_ * D_];
__device__ __align__(16) __half g_Wqkv[(size_t)D_ * 3 * D_];
__device__ __align__(16) __half g_Woh [D_ * D_];
__device__ __align__(16) __half g_W1h [(size_t)D_ * FFN_];
__device__ __align__(16) __half g_W2h [(size_t)FFN_ * D_];
__device__ __align__(16) __half g_qh  [BL_ * D_];
__device__ __align__(16) __half g_kh  [BL_ * D_];
__device__ __align__(16) __half g_vh  [BL_ * D_];
__device__ __align__(16) __half g_ch  [BL_ * D_];
__device__ __align__(16) __half g_h1h [BL_ * D_];
__device__ __align__(16) __half g_fh  [(size_t)BL_ * FFN_];
__device__ __align__(16) __half g_Ph  [(size_t)B_ * NH_ * L_ * L_];
__device__ float g_S  [(size_t)B_ * NH_ * L_ * L_];
__device__ float g_hsa[BL_ * D_];
__device__ float g_h1 [BL_ * D_];
__device__ float g_hf [BL_ * D_];
__device__ float g_rq [BL_ * 4];
__device__ float g_rk [BL_ * 4];

// ---------------- asm helpers ----------------
#define LDSM4(R, addr) asm volatile( \
    "ldmatrix.sync.aligned.m8n8.x4.shared.b16 {%0,%1,%2,%3}, [%4];" \
    : "=r"((R)[0]), "=r"((R)[1]), "=r"((R)[2]), "=r"((R)[3]) : "r"(addr))

#define LDSM4T(R, addr) asm volatile( \
    "ldmatrix.sync.aligned.m8n8.x4.trans.shared.b16 {%0,%1,%2,%3}, [%4];" \
    : "=r"((R)[0]), "=r"((R)[1]), "=r"((R)[2]), "=r"((R)[3]) : "r"(addr))

#define MMA16816(AC, A, B0, B1) asm volatile( \
    "mma.sync.aligned.m16n8k16.row.col.f32.f16.f16.f32 " \
    "{%0,%1,%2,%3},{%4,%5,%6,%7},{%8,%9},{%0,%1,%2,%3};" \
    : "+f"((AC)[0]), "+f"((AC)[1]), "+f"((AC)[2]), "+f"((AC)[3]) \
    : "r"((A)[0]), "r"((A)[1]), "r"((A)[2]), "r"((A)[3]), "r"(B0), "r"(B1))

#define CPA16(dst, src) asm volatile( \
    "cp.async.cg.shared.global [%0], [%1], 16;" :: "r"(dst), "l"(src))

// ---------------- unified fp16 tensor-core GEMM ----------------
// Warp tile fixed 64x64; CTA tile (WR*64) x ((8/WR)*64); BK=64, 3-stage cp.async.
// C = op(alpha * A@B + bias). A: [M,K] row-major. B: [K,N] row-major.
// nSplit routes 1024-wide output column groups to C0/C1/C2 (fused QKV).
template <int BMT, int BNT, int WR, int MINB>
__global__ __launch_bounds__(256, MINB)
void gemm_f16_t(const __half* __restrict__ Ah, const __half* __restrict__ Bh,
                const float* __restrict__ bias,
                float* __restrict__ Cf, __half* __restrict__ C0,
                __half* __restrict__ C1, __half* __restrict__ C2,
                int K, int lda, int ldb, int ldc,
                long long sA, long long sB, long long sC,
                float alpha, int doBias, int doRelu, int nSplit)
{
    constexpr int BPITCH = BNT + 8;
    constexpr int A_PL = BMT * APITCH * 2;
    constexpr int B_PL = BK * BPITCH * 2;
    constexpr int STAGE_B = A_PL + B_PL;
    constexpr int WCN = 8 / WR;              // warps in N
    constexpr int ACN = BMT / 32;            // A 16B-chunks per thread
    constexpr int BCN = BNT / 32;            // B 16B-chunks per thread
    constexpr int BROWCHK = BNT / 8;         // 16B chunks per B row

    extern __shared__ char smem[];
    const unsigned smemS = (unsigned)__cvta_generic_to_shared(smem);
    const int tid = threadIdx.x, lane = tid & 31, w = tid >> 5;

    const int bz = blockIdx.z;
    int rowTile = blockIdx.y * BMT, colTile = blockIdx.x * BNT;
    const __half* pA = Ah + (long long)bz * sA + (long long)rowTile * lda;
    const __half* pB = Bh + (long long)bz * sB + colTile;
    const long long cOff = (long long)bz * sC;

    __half* Ch = C0;
    if (nSplit) {
        const int sel = colTile >> 10;
        Ch = (sel == 0) ? C0 : (sel == 1) ? C1 : C2;
        colTile &= 1023;
    }

    const int wRow = (w / WCN) * 64, wCol = (w % WCN) * 64;
    const int nT = K / BK;

    auto load_stage = [&](int slot, int k0) {
        const unsigned base = smemS + (unsigned)slot * STAGE_B;
#pragma unroll
        for (int i = 0; i < ACN; i++) {
            const int u = tid + i * 256;
            const int r = u >> 3, p = u & 7;
            CPA16(base + (unsigned)((r * APITCH + p * 8) * 2),
                  pA + (long long)r * lda + k0 + p * 8);
        }
#pragma unroll
        for (int i = 0; i < BCN; i++) {
            const int u = tid + i * 256;
            const int r = u / BROWCHK, p = u % BROWCHK;
            CPA16(base + A_PL + (unsigned)((r * BPITCH + p * 8) * 2),
                  pB + (long long)(k0 + r) * ldb + p * 8);
        }
        asm volatile("cp.async.commit_group;");
    };

    const int aLR = lane & 15, aLC = (lane >> 4) * 8;
    const int bLR = ((lane >> 3) & 1) * 8 + (lane & 7);
    const int bLC = (lane >> 4) * 8;

    float acc[4][8][4];
#pragma unroll
    for (int i = 0; i < 4; i++)
#pragma unroll
        for (int j = 0; j < 8; j++)
#pragma unroll
            for (int e = 0; e < 4; e++) acc[i][j][e] = 0.f;

    load_stage(0, 0);
    load_stage(1, (1 < nT ? 1 : nT - 1) * BK);

    for (int t = 0; t < nT; ++t) {
        asm volatile("cp.async.wait_group 1;" ::: "memory");
        __syncthreads();
        {
            const int s = t + 2;
            load_stage((t + 2) % STAGES, (s < nT ? s : nT - 1) * BK);
        }
        const unsigned sb = smemS + (unsigned)(t % STAGES) * STAGE_B;
#pragma unroll
        for (int kk = 0; kk < BK / 16; kk++) {
            unsigned ah[4][4], bh[4][4];
#pragma unroll
            for (int mi = 0; mi < 4; mi++) {
                unsigned adr = sb +
                    (unsigned)(((wRow + mi * 16 + aLR) * APITCH + kk * 16 + aLC) << 1);
                LDSM4(ah[mi], adr);
            }
#pragma unroll
            for (int np = 0; np < 4; np++) {
                unsigned adr = sb + A_PL +
                    (unsigned)(((kk * 16 + bLR) * BPITCH + wCol + np * 16 + bLC) << 1);
                LDSM4T(bh[np], adr);
            }
#pragma unroll
            for (int mi = 0; mi < 4; mi++)
#pragma unroll
                for (int ni = 0; ni < 8; ni++)
                    MMA16816(acc[mi][ni], ah[mi],
                             bh[ni >> 1][(ni & 1) * 2], bh[ni >> 1][(ni & 1) * 2 + 1]);
        }
    }

    // epilogue
#pragma unroll
    for (int mi = 0; mi < 4; mi++)
#pragma unroll
        for (int ni = 0; ni < 8; ni++) {
            const int r0 = rowTile + wRow + mi * 16 + (lane >> 2);
            const int c  = colTile + wCol + ni * 8 + (lane & 3) * 2;
            float* a = acc[mi][ni];
#pragma unroll
            for (int hrow = 0; hrow < 2; hrow++) {
                const int r = r0 + hrow * 8;
                float o0 = alpha * a[hrow * 2 + 0];
                float o1 = alpha * a[hrow * 2 + 1];
                if (doBias) { o0 += bias[c]; o1 += bias[c + 1]; }
                if (doRelu) { o0 = fmaxf(o0, 0.f); o1 = fmaxf(o1, 0.f); }
                const long long idx = cOff + (long long)r * ldc + c;
                if (Cf) {
                    *(float2*)&Cf[idx] = make_float2(o0, o1);
                } else {
                    __half2 p; p.x = __float2half_rn(o0); p.y = __float2half_rn(o1);
                    *(__half2*)&Ch[idx] = p;
                }
            }
        }
}

// ---------------- batched fp32 -> fp16 convert (up to 4 tensors) -----------
__global__ __launch_bounds__(256)
void conv4_kernel(const float* __restrict__ s0, const float* __restrict__ s1,
                  const float* __restrict__ s2, const float* __restrict__ s3,
                  __half* __restrict__ o0, __half* __restrict__ o1,
                  __half* __restrict__ o2, __half* __restrict__ o3,
                  long long n0, long long n1, long long n2, long long n3)
{
    long long i = ((long long)blockIdx.x * 256 + threadIdx.x) * 8;
    const float* s; __half* o;
    if (i < n0)                     { s = s0; o = o0; }
    else if ((i -= n0) < n1)        { s = s1; o = o1; }
    else if ((i -= n1) < n2)        { s = s2; o = o2; }
    else if ((i -= n2) < n3)        { s = s3; o = o3; }
    else return;
    float4 v0 = *(const float4*)(s + i);
    float4 v1 = *(const float4*)(s + i + 4);
    __half2 r[4];
    r[0].x = __float2half_rn(v0.x); r[0].y = __float2half_rn(v0.y);
    r[1].x = __float2half_rn(v0.z); r[1].y = __float2half_rn(v0.w);
    r[2].x = __float2half_rn(v1.x); r[2].y = __float2half_rn(v1.y);
    r[3].x = __float2half_rn(v1.z); r[3].y = __float2half_rn(v1.w);
    *(uint4*)&o[i] = *(uint4*)r;
}

// fp32 [D,D] -> fp16 into packed [D, 3D] buffer at column offset
__global__ __launch_bounds__(256)
void convpack_kernel(const float* __restrict__ s, __half* __restrict__ o,
                     int colOff)
{
    const long long i = ((long long)blockIdx.x * 256 + threadIdx.x) * 8;
    if (i >= (long long)D_ * D_) return;
    const int row = (int)(i >> 10), col = (int)(i & 1023);
    float4 v0 = *(const float4*)(s + i);
    float4 v1 = *(const float4*)(s + i + 4);
    __half2 r[4];
    r[0].x = __float2half_rn(v0.x); r[0].y = __float2half_rn(v0.y);
    r[1].x = __float2half_rn(v0.z); r[1].y = __float2half_rn(v0.w);
    r[2].x = __float2half_rn(v1.x); r[2].y = __float2half_rn(v1.y);
    r[3].x = __float2half_rn(v1.z); r[3].y = __float2half_rn(v1.w);
    *(uint4*)&o[(long long)row * (3 * D_) + colOff + col] = *(uint4*)r;
}

// ---------------- rank-4 relative projections ----------------
__global__ void rproj_kernel(const float* __restrict__ rh,
                             const float* __restrict__ Wrq,
                             const float* __restrict__ Wrk,
                             float* __restrict__ rq, float* __restrict__ rk)
{
    const int i = blockIdx.x * blockDim.x + threadIdx.x;
    if (i >= BL_) return;
    const float h0 = rh[i * 4 + 0], h1v = rh[i * 4 + 1];
    const float h2 = rh[i * 4 + 2], h3 = rh[i * 4 + 3];
#pragma unroll
    for (int r = 0; r < 4; r++) {
        rq[i * 4 + r] = h0 * Wrq[r] + h1v * Wrq[4 + r] + h2 * Wrq[8 + r] + h3 * Wrq[12 + r];
        rk[i * 4 + r] = h0 * Wrk[r] + h1v * Wrk[4 + r] + h2 * Wrk[8 + r] + h3 * Wrk[12 + r];
    }
}

// ---------------- block reduction ----------------
__device__ __forceinline__ float blockReduce(float v, float* red, bool isMax)
{
    __syncthreads();
#pragma unroll
    for (int o = 16; o > 0; o >>= 1) {
        float t = __shfl_xor_sync(0xffffffffu, v, o);
        v = isMax ? fmaxf(v, t) : (v + t);
    }
    const int warp = threadIdx.x >> 5, lane = threadIdx.x & 31;
    if (lane == 0) red[warp] = v;
    __syncthreads();
    if (warp == 0) {
        v = (lane < 8) ? red[lane] : (isMax ? -INFINITY : 0.f);
#pragma unroll
        for (int o = 4; o > 0; o >>= 1) {
            float t = __shfl_xor_sync(0xffffffffu, v, o);
            v = isMax ? fmaxf(v, t) : (v + t);
        }
        if (lane == 0) red[0] = v;
    }
    __syncthreads();
    return red[0];
}

// ---------------- fused rel-bias + softmax -> fp16 ----------------
__global__ __launch_bounds__(256)
void softmax_bias_kernel(const float* __restrict__ S,
                         const float* __restrict__ rq,
                         const float* __restrict__ rk,
                         __half* __restrict__ Ph)
{
    __shared__ float red[32];
    const int l = blockIdx.x, n = blockIdx.y, b = blockIdx.z;
    const long long rowOff = ((((long long)b * NH_ + n) * L_) + l) * L_;
    const float* row = S + rowOff;
    const float* rqp = rq + ((long long)b * L_ + l) * 4;
    const float* rkp = rk + (long long)b * L_ * 4;
    const float q0 = rqp[0] * 0.5f, q1 = rqp[1] * 0.5f;
    const float q2 = rqp[2] * 0.5f, q3 = rqp[3] * 0.5f;
    const int tid = threadIdx.x;

    float vals[8];
    float vmax = -INFINITY;
#pragma unroll
    for (int j = 0; j < 8; j++) {
        const int m = j * 256 + tid;
        const float bias = q0 * rkp[m] + q1 * rkp[L_ + m]
                         + q2 * rkp[2 * L_ + m] + q3 * rkp[3 * L_ + m];
        const float v = row[m] + bias;
        vals[j] = v;
        vmax = fmaxf(vmax, v);
    }
    vmax = blockReduce(vmax, red, true);

    float sum = 0.f;
#pragma unroll
    for (int j = 0; j < 8; j++) {
        vals[j] = __expf(vals[j] - vmax);
        sum += vals[j];
    }
    sum = blockReduce(sum, red, false);
    const float inv = 1.f / sum;
#pragma unroll
    for (int j = 0; j < 8; j++)
        Ph[rowOff + j * 256 + tid] = __float2half_rn(vals[j] * inv);
}

// ---------------- fused residual-add + LayerNorm (+ optional fp16 out) -----
__global__ __launch_bounds__(256)
void add_ln_kernel(const float* __restrict__ x, const float* __restrict__ y,
                   const float* __restrict__ g, const float* __restrict__ be,
                   float* __restrict__ outF, __half* __restrict__ outH)
{
    __shared__ float red[32];
    const long long row = blockIdx.x;
    const float* xp = x + row * D_;
    const float* yp = y + row * D_;
    const int tid = threadIdx.x;

    float v[4];
    float s = 0.f;
#pragma unroll
    for (int j = 0; j < 4; j++) {
        const int i = j * 256 + tid;
        v[j] = xp[i] + yp[i];
        s += v[j];
    }
    const float mean = blockReduce(s, red, false) * (1.f / D_);

    float sq = 0.f;
#pragma unroll
    for (int j = 0; j < 4; j++) {
        const float d = v[j] - mean;
        sq += d * d;
    }
    const float var = blockReduce(sq, red, false) * (1.f / D_);
    const float rstd = rsqrtf(var + LN_EPS);
#pragma unroll
    for (int j = 0; j < 4; j++) {
        const int i = j * 256 + tid;
        const float o = (v[j] - mean) * rstd * g[i] + be[i];
        outF[row * D_ + i] = o;
        if (outH) outH[row * D_ + i] = __float2half_rn(o);
    }
}

// ---------------- host helpers ----------------
#define SMEM_W (STAGES * (128 * APITCH * 2 + BK * (256 + 8) * 2))   // wide 156672
#define SMEM_M (STAGES * (256 * APITCH * 2 + BK * (128 + 8) * 2))   // M-heavy 162816

static void gemmW(const __half* Ah, const __half* Bh,
                  const float* bias, float* Cf, __half* Ch,
                  int M, int N, int K, int lda, int ldb, int ldc,
                  long long sA, long long sB, long long sC, int batch,
                  float alpha, int doBias, int doRelu,
                  __half* C1 = nullptr, __half* C2 = nullptr, int nSplit = 0)
{
    dim3 grid(N / 256, M / 128, batch), block(256);
    gemm_f16_t<128, 256, 2, 1><<<grid, block, SMEM_W>>>(Ah, Bh, bias, Cf, Ch, C1, C2,
                                                        K, lda, ldb, ldc, sA, sB, sC,
                                                        alpha, doBias, doRelu, nSplit);
}

static void gemmM(const __half* Ah, const __half* Bh,
                  const float* bias, float* Cf, __half* Ch,
                  int M, int N, int K, int lda, int ldb, int ldc,
                  long long sA, long long sB, long long sC, int batch,
                  float alpha, int doBias, int doRelu)
{
    dim3 grid(N / 128, M / 256, batch), block(256);
    gemm_f16_t<256, 128, 4, 1><<<grid, block, SMEM_M>>>(Ah, Bh, bias, Cf, Ch, nullptr, nullptr,
                                                        K, lda, ldb, ldc, sA, sB, sC,
                                                        alpha, doBias, doRelu, 0);
}

template <typename T>
static T* sym(T* symbol) { void* p; cudaGetSymbolAddress(&p, (const void*)symbol); return (T*)p; }

extern "C" void kernel_launch(void* const* d_in, const int* in_sizes, int n_in,
                              void* d_out, int out_size)
{
    const float* h   = (const float*)d_in[0];
    const float* rh  = (const float*)d_in[1];
    const float* Wq  = (const float*)d_in[2];
    const float* Wk  = (const float*)d_in[3];
    const float* Wv  = (const float*)d_in[4];
    const float* Wo  = (const float*)d_in[5];
    const float* Wrk = (const float*)d_in[6];
    const float* Wrq = (const float*)d_in[7];
    const float* W1  = (const float*)d_in[8];
    const float* b1  = (const float*)d_in[9];
    const float* W2  = (const float*)d_in[10];
    const float* b2  = (const float*)d_in[11];
    const float* g1  = (const float*)d_in[12];
    const float* be1 = (const float*)d_in[13];
    const float* g2  = (const float*)d_in[14];
    const float* be2 = (const float*)d_in[15];
    float* out = (float*)d_out;

    cudaFuncSetAttribute((const void*)gemm_f16_t<128, 256, 2, 1>,
                         cudaFuncAttributeMaxDynamicSharedMemorySize, SMEM_W);
    cudaFuncSetAttribute((const void*)gemm_f16_t<256, 128, 4, 1>,
                         cudaFuncAttributeMaxDynamicSharedMemorySize, SMEM_M);

    __half *hh = sym(g_hh), *Wqkv = sym(g_Wqkv);
    __half *Woh = sym(g_Woh), *W1h = sym(g_W1h), *W2h = sym(g_W2h);
    __half *qh = sym(g_qh), *kh = sym(g_kh), *vh = sym(g_vh);
    __half *ch = sym(g_ch), *h1h = sym(g_h1h), *fh = sym(g_fh);
    __half *Ph = sym(g_Ph);
    float *S = sym(g_S), *hsa = sym(g_hsa), *h1 = sym(g_h1), *hf = sym(g_hf);
    float *rq = sym(g_rq), *rk = sym(g_rk);

    const long long nH = (long long)BL_ * D_;
    const long long nW = (long long)D_ * D_;
    const long long nF = (long long)D_ * FFN_;
    const int cgrid = (int)(nW / 2048);

    // converts: h + packed QKV weights
    conv4_kernel<<<(int)(nH / 2048), 256>>>(h, nullptr, nullptr, nullptr,
                                            hh, nullptr, nullptr, nullptr, nH, 0, 0, 0);
    convpack_kernel<<<cgrid, 256>>>(Wq, Wqkv, 0);
    convpack_kernel<<<cgrid, 256>>>(Wk, Wqkv, D_);
    convpack_kernel<<<cgrid, 256>>>(Wv, Wqkv, 2 * D_);
    // fused QKV projection
    gemmW(hh, Wqkv, nullptr, nullptr, qh, BL_, 3 * D_, D_, D_, 3 * D_, D_,
          0, 0, 0, 1, 1.f, 0, 0, kh, vh, 1);
    // scores: per (b,head), S = Q @ Kt / sqrt(HD)
    gemmW(qh, kh, nullptr, S, nullptr, L_, L_, HD_, HD_, L_, L_,
          CHUNK_, CHUNK_, (long long)L_ * L_, B_ * NH_, RSQRT_HD, 0, 0);
    // rank-4 projections
    rproj_kernel<<<BL_ / 256, 256>>>(rh, Wrq, Wrk, rq, rk);
    // convert Wo, W1, W2
    conv4_kernel<<<(int)((nW + 2 * nF) / 2048), 256>>>(
        Wo, W1, W2, nullptr, Woh, W1h, W2h, nullptr, nW, nF, nF, 0);
    // fused rel-bias + softmax -> P fp16
    {
        dim3 grid(L_, NH_, B_);
        softmax_bias_kernel<<<grid, 256>>>(S, rq, rk, Ph);
    }
    // context: P @ V (M-heavy tile, 128 CTAs = one wave)
    gemmM(Ph, vh, nullptr, nullptr, ch, L_, HD_, L_, L_, HD_, HD_,
          (long long)L_ * L_, CHUNK_, CHUNK_, B_ * NH_, 1.f, 0, 0);
    // output projection
    gemmW(ch, Woh, nullptr, hsa, nullptr, BL_, D_, D_, D_, D_, D_, 0, 0, 0, 1, 1.f, 0, 0);
    // h1 = LN(hsa + h)
    add_ln_kernel<<<BL_, 256>>>(hsa, h, g1, be1, h1, h1h);
    // FFN up
    gemmW(h1h, W1h, b1, nullptr, fh, BL_, FFN_, D_, D_, FFN_, FFN_, 0, 0, 0, 1, 1.f, 1, 1);
    // FFN down
    gemmW(fh, W2h, b2, hf, nullptr, BL_, D_, FFN_, FFN_, D_, D_, 0, 0, 0, 1, 1.f, 1, 0);
    // h2 = LN(h1 + hf) -> out
    add_ln_kernel<<<BL_, 256>>>(h1, hf, g2, be2, out, nullptr);
}

// round 17
// speedup vs baseline: 1.2935x; 1.2149x over previous
#include <cuda_runtime.h>
#include <cuda_fp16.h>
#include <math.h>

#define B_    2
#define L_    2048
#define D_    1024
#define FFN_  4096
#define NH_   8
#define HD_   128
#define BL_   (B_ * L_)
#define CHUNK_ ((long long)L_ * HD_)
#define LN_EPS 1e-5f
#define RSQRT_HD 0.08838834764831845f

#define BK 64
#define STAGES 3
#define APITCH (BK + 8)                    // 72 halfs per A smem row

// ---------------- scratch (device globals: allocation-free) ----------------
__device__ __align__(16) __half g_hh  [BL_ * D_];
__device__ __align__(16) __half g_Wqkv[(size_t)D_ * 3 * D_];
__device__ __align__(16) __half g_Woh [D_ * D_];
__device__ __align__(16) __half g_W1h [(size_t)D_ * FFN_];
__device__ __align__(16) __half g_W2h [(size_t)FFN_ * D_];
__device__ __align__(16) __half g_qh  [BL_ * D_];
__device__ __align__(16) __half g_kh  [BL_ * D_];
__device__ __align__(16) __half g_vh  [BL_ * D_];
__device__ __align__(16) __half g_ch  [BL_ * D_];
__device__ __align__(16) __half g_h1h [BL_ * D_];
__device__ __align__(16) __half g_fh  [(size_t)BL_ * FFN_];
__device__ float g_hsa[BL_ * D_];
__device__ float g_h1 [BL_ * D_];
__device__ float g_hf [BL_ * D_];
__device__ __align__(16) float g_rq [BL_ * 4];
__device__ __align__(16) float g_rk [BL_ * 4];

// ---------------- asm helpers ----------------
#define LDSM4(R, addr) asm volatile( \
    "ldmatrix.sync.aligned.m8n8.x4.shared.b16 {%0,%1,%2,%3}, [%4];" \
    : "=r"((R)[0]), "=r"((R)[1]), "=r"((R)[2]), "=r"((R)[3]) : "r"(addr))

#define LDSM4T(R, addr) asm volatile( \
    "ldmatrix.sync.aligned.m8n8.x4.trans.shared.b16 {%0,%1,%2,%3}, [%4];" \
    : "=r"((R)[0]), "=r"((R)[1]), "=r"((R)[2]), "=r"((R)[3]) : "r"(addr))

#define MMA16816(AC, A, B0, B1) asm volatile( \
    "mma.sync.aligned.m16n8k16.row.col.f32.f16.f16.f32 " \
    "{%0,%1,%2,%3},{%4,%5,%6,%7},{%8,%9},{%0,%1,%2,%3};" \
    : "+f"((AC)[0]), "+f"((AC)[1]), "+f"((AC)[2]), "+f"((AC)[3]) \
    : "r"((A)[0]), "r"((A)[1]), "r"((A)[2]), "r"((A)[3]), "r"(B0), "r"(B1))

#define CPA16(dst, src) asm volatile( \
    "cp.async.cg.shared.global [%0], [%1], 16;" :: "r"(dst), "l"(src))

// ---------------- unified fp16 tensor-core GEMM (from R14) ----------------
template <int BMT, int BNT, int WR, int MINB>
__global__ __launch_bounds__(256, MINB)
void gemm_f16_t(const __half* __restrict__ Ah, const __half* __restrict__ Bh,
                const float* __restrict__ bias,
                float* __restrict__ Cf, __half* __restrict__ C0,
                __half* __restrict__ C1, __half* __restrict__ C2,
                int K, int lda, int ldb, int ldc,
                long long sA, long long sB, long long sC,
                float alpha, int doBias, int doRelu, int nSplit)
{
    constexpr int BPITCH = BNT + 8;
    constexpr int A_PL = BMT * APITCH * 2;
    constexpr int B_PL = BK * BPITCH * 2;
    constexpr int STAGE_B = A_PL + B_PL;
    constexpr int WCN = 8 / WR;
    constexpr int ACN = BMT / 32;
    constexpr int BCN = BNT / 32;
    constexpr int BROWCHK = BNT / 8;

    extern __shared__ char smem[];
    const unsigned smemS = (unsigned)__cvta_generic_to_shared(smem);
    const int tid = threadIdx.x, lane = tid & 31, w = tid >> 5;

    const int bz = blockIdx.z;
    int rowTile = blockIdx.y * BMT, colTile = blockIdx.x * BNT;
    const __half* pA = Ah + (long long)bz * sA + (long long)rowTile * lda;
    const __half* pB = Bh + (long long)bz * sB + colTile;
    const long long cOff = (long long)bz * sC;

    __half* Ch = C0;
    if (nSplit) {
        const int sel = colTile >> 10;
        Ch = (sel == 0) ? C0 : (sel == 1) ? C1 : C2;
        colTile &= 1023;
    }

    const int wRow = (w / WCN) * 64, wCol = (w % WCN) * 64;
    const int nT = K / BK;

    auto load_stage = [&](int slot, int k0) {
        const unsigned base = smemS + (unsigned)slot * STAGE_B;
#pragma unroll
        for (int i = 0; i < ACN; i++) {
            const int u = tid + i * 256;
            const int r = u >> 3, p = u & 7;
            CPA16(base + (unsigned)((r * APITCH + p * 8) * 2),
                  pA + (long long)r * lda + k0 + p * 8);
        }
#pragma unroll
        for (int i = 0; i < BCN; i++) {
            const int u = tid + i * 256;
            const int r = u / BROWCHK, p = u % BROWCHK;
            CPA16(base + A_PL + (unsigned)((r * BPITCH + p * 8) * 2),
                  pB + (long long)(k0 + r) * ldb + p * 8);
        }
        asm volatile("cp.async.commit_group;");
    };

    const int aLR = lane & 15, aLC = (lane >> 4) * 8;
    const int bLR = ((lane >> 3) & 1) * 8 + (lane & 7);
    const int bLC = (lane >> 4) * 8;

    float acc[4][8][4];
#pragma unroll
    for (int i = 0; i < 4; i++)
#pragma unroll
        for (int j = 0; j < 8; j++)
#pragma unroll
            for (int e = 0; e < 4; e++) acc[i][j][e] = 0.f;

    load_stage(0, 0);
    load_stage(1, (1 < nT ? 1 : nT - 1) * BK);

    for (int t = 0; t < nT; ++t) {
        asm volatile("cp.async.wait_group 1;" ::: "memory");
        __syncthreads();
        {
            const int s = t + 2;
            load_stage((t + 2) % STAGES, (s < nT ? s : nT - 1) * BK);
        }
        const unsigned sb = smemS + (unsigned)(t % STAGES) * STAGE_B;
#pragma unroll
        for (int kk = 0; kk < BK / 16; kk++) {
            unsigned ah[4][4], bh[4][4];
#pragma unroll
            for (int mi = 0; mi < 4; mi++) {
                unsigned adr = sb +
                    (unsigned)(((wRow + mi * 16 + aLR) * APITCH + kk * 16 + aLC) << 1);
                LDSM4(ah[mi], adr);
            }
#pragma unroll
            for (int np = 0; np < 4; np++) {
                unsigned adr = sb + A_PL +
                    (unsigned)(((kk * 16 + bLR) * BPITCH + wCol + np * 16 + bLC) << 1);
                LDSM4T(bh[np], adr);
            }
#pragma unroll
            for (int mi = 0; mi < 4; mi++)
#pragma unroll
                for (int ni = 0; ni < 8; ni++)
                    MMA16816(acc[mi][ni], ah[mi],
                             bh[ni >> 1][(ni & 1) * 2], bh[ni >> 1][(ni & 1) * 2 + 1]);
        }
    }

#pragma unroll
    for (int mi = 0; mi < 4; mi++)
#pragma unroll
        for (int ni = 0; ni < 8; ni++) {
            const int r0 = rowTile + wRow + mi * 16 + (lane >> 2);
            const int c  = colTile + wCol + ni * 8 + (lane & 3) * 2;
            float* a = acc[mi][ni];
#pragma unroll
            for (int hrow = 0; hrow < 2; hrow++) {
                const int r = r0 + hrow * 8;
                float o0 = alpha * a[hrow * 2 + 0];
                float o1 = alpha * a[hrow * 2 + 1];
                if (doBias) { o0 += bias[c]; o1 += bias[c + 1]; }
                if (doRelu) { o0 = fmaxf(o0, 0.f); o1 = fmaxf(o1, 0.f); }
                const long long idx = cOff + (long long)r * ldc + c;
                if (Cf) {
                    *(float2*)&Cf[idx] = make_float2(o0, o1);
                } else {
                    __half2 p; p.x = __float2half_rn(o0); p.y = __float2half_rn(o1);
                    *(__half2*)&Ch[idx] = p;
                }
            }
        }
}

// ---------------- fused flash attention (rel-bias + online softmax) --------
// NOTE: reference "K^T" is a FLAT REINTERPRET: Kt[d][m] = kflat[d*L + m].
// K tile is therefore loaded from the [HD, L] view (row d, ld = L) and used
// exactly like the GEMM's [k, n] row-major B operand (LDSM4T).
#define FA_PITCH 136
#define FA_TILE_B (128 * FA_PITCH * 2)                  // 34816 bytes
#define FA_K_OFF(buf) (FA_TILE_B + (buf) * 2 * FA_TILE_B)
#define FA_V_OFF(buf) (FA_TILE_B + (buf) * 2 * FA_TILE_B + FA_TILE_B)
#define FA_RK_OFF(buf) (5 * FA_TILE_B + (buf) * 2048)
#define FA_SMEM (5 * FA_TILE_B + 2 * 2048)              // 178176 bytes

__global__ __launch_bounds__(256, 1)
void flash_attn_kernel(const __half* __restrict__ Q, const __half* __restrict__ Kg,
                       const __half* __restrict__ Vg,
                       const float* __restrict__ rqg, const float* __restrict__ rkg,
                       __half* __restrict__ O)
{
    extern __shared__ char smem[];
    const unsigned smemS = (unsigned)__cvta_generic_to_shared(smem);
    const int tid = threadIdx.x, lane = tid & 31, w = tid >> 5;
    const int bh = blockIdx.z;                 // b*NH + h
    const int b = bh >> 3;
    const int qt = blockIdx.x;                 // Q tile index
    const long long chunk = (long long)bh * CHUNK_;
    const __half* pQ = Q + chunk + (long long)qt * 128 * HD_;
    const __half* pK = Kg + chunk;             // [HD, L] flat view: K[d*L + m]
    const __half* pV = Vg + chunk;             // [L, HD] view: V[m*HD + d]
    const float* rkf = rkg + (long long)b * L_ * 4;

    // prologue: Q tile (rows of 128 halfs = 16 chunks/row; 2048 chunks total)
#pragma unroll
    for (int i = 0; i < 8; i++) {
        const int u = tid + i * 256;
        const int r = u >> 4, p = u & 15;
        CPA16(smemS + (unsigned)((r * FA_PITCH + p * 8) * 2),
              pQ + (long long)r * HD_ + p * 8);
    }
    asm volatile("cp.async.commit_group;");

    auto load_stage = [&](int buf, int t) {
        const long long m0 = (long long)t * 128;
#pragma unroll
        for (int i = 0; i < 8; i++) {
            const int u = tid + i * 256;
            const int r = u >> 4, p = u & 15;
            const unsigned off = (unsigned)((r * FA_PITCH + p * 8) * 2);
            // K: row d = r of [HD, L] view, cols m0..m0+127
            CPA16(smemS + FA_K_OFF(buf) + off, pK + (long long)r * L_ + m0 + p * 8);
            // V: row m = m0 + r of [L, HD] view
            CPA16(smemS + FA_V_OFF(buf) + off, pV + (m0 + r) * HD_ + p * 8);
        }
        if (tid < 128) {
            const int r = tid >> 5, c4 = (tid & 31) * 4;
            CPA16(smemS + FA_RK_OFF(buf) + (unsigned)((r * 128 + c4) * 4),
                  rkf + (long long)r * L_ + m0 + c4);
        }
        asm volatile("cp.async.commit_group;");
    };
    load_stage(0, 0);

    // per-thread rq (two rows), pre-scaled by 0.5
    const int rowL = qt * 128 + w * 16 + (lane >> 2);
    float4 rql = *(const float4*)(rqg + ((long long)b * L_ + rowL) * 4);
    float4 rqh = *(const float4*)(rqg + ((long long)b * L_ + rowL + 8) * 4);
    rql.x *= 0.5f; rql.y *= 0.5f; rql.z *= 0.5f; rql.w *= 0.5f;
    rqh.x *= 0.5f; rqh.y *= 0.5f; rqh.z *= 0.5f; rqh.w *= 0.5f;

    const int aLR = lane & 15, aLC = (lane >> 4) * 8;
    const int bLR = ((lane >> 3) & 1) * 8 + (lane & 7);
    const int bLC = (lane >> 4) * 8;

    float oacc[16][4];
#pragma unroll
    for (int i = 0; i < 16; i++)
#pragma unroll
        for (int e = 0; e < 4; e++) oacc[i][e] = 0.f;
    float mLo = -1e30f, mHi = -1e30f, lLo = 0.f, lHi = 0.f;
    unsigned qf[8][4];

    for (int t = 0; t < 16; ++t) {
        const int buf = t & 1;
        if (t + 1 < 16) {
            load_stage(buf ^ 1, t + 1);
            asm volatile("cp.async.wait_group 1;" ::: "memory");
        } else {
            asm volatile("cp.async.wait_group 0;" ::: "memory");
        }
        __syncthreads();

        if (t == 0) {
#pragma unroll
            for (int ks = 0; ks < 8; ks++) {
                unsigned adr = smemS +
                    (unsigned)(((w * 16 + aLR) * FA_PITCH + ks * 16 + aLC) << 1);
                LDSM4(qf[ks], adr);
            }
        }

        // ---- S[l][m] = sum_d Q[l,d] * Ktile[d][m]  (B = [k=d][n=m], LDSM4T) ----
        float sacc[16][4];
#pragma unroll
        for (int i = 0; i < 16; i++)
#pragma unroll
            for (int e = 0; e < 4; e++) sacc[i][e] = 0.f;
#pragma unroll
        for (int nb = 0; nb < 8; nb++) {
#pragma unroll
            for (int ks = 0; ks < 8; ks++) {
                unsigned kf[4];
                unsigned adr = smemS + FA_K_OFF(buf) +
                    (unsigned)(((ks * 16 + bLR) * FA_PITCH + nb * 16 + bLC) << 1);
                LDSM4T(kf, adr);
                MMA16816(sacc[2 * nb],     qf[ks], kf[0], kf[1]);
                MMA16816(sacc[2 * nb + 1], qf[ks], kf[2], kf[3]);
            }
        }

        // ---- scale + rel-bias + row max ----
        const float* rkS = (const float*)(smem + FA_RK_OFF(buf));
        float rmLo = -1e30f, rmHi = -1e30f;
#pragma unroll
        for (int ni = 0; ni < 16; ni++) {
            const int c = ni * 8 + (lane & 3) * 2;
            const float k0 = rkS[c],       k1 = rkS[128 + c],
                        k2 = rkS[256 + c], k3 = rkS[384 + c];
            const float j0 = rkS[c + 1],       j1 = rkS[128 + c + 1],
                        j2 = rkS[256 + c + 1], j3 = rkS[384 + c + 1];
            const float bL0 = rql.x * k0 + rql.y * k1 + rql.z * k2 + rql.w * k3;
            const float bL1 = rql.x * j0 + rql.y * j1 + rql.z * j2 + rql.w * j3;
            const float bH0 = rqh.x * k0 + rqh.y * k1 + rqh.z * k2 + rqh.w * k3;
            const float bH1 = rqh.x * j0 + rqh.y * j1 + rqh.z * j2 + rqh.w * j3;
            sacc[ni][0] = sacc[ni][0] * RSQRT_HD + bL0;
            sacc[ni][1] = sacc[ni][1] * RSQRT_HD + bL1;
            sacc[ni][2] = sacc[ni][2] * RSQRT_HD + bH0;
            sacc[ni][3] = sacc[ni][3] * RSQRT_HD + bH1;
            rmLo = fmaxf(rmLo, fmaxf(sacc[ni][0], sacc[ni][1]));
            rmHi = fmaxf(rmHi, fmaxf(sacc[ni][2], sacc[ni][3]));
        }
        rmLo = fmaxf(rmLo, __shfl_xor_sync(0xffffffffu, rmLo, 1));
        rmLo = fmaxf(rmLo, __shfl_xor_sync(0xffffffffu, rmLo, 2));
        rmHi = fmaxf(rmHi, __shfl_xor_sync(0xffffffffu, rmHi, 1));
        rmHi = fmaxf(rmHi, __shfl_xor_sync(0xffffffffu, rmHi, 2));

        const float mNewLo = fmaxf(mLo, rmLo);
        const float mNewHi = fmaxf(mHi, rmHi);
        const float sfLo = __expf(mLo - mNewLo);
        const float sfHi = __expf(mHi - mNewHi);
        mLo = mNewLo; mHi = mNewHi;
        lLo *= sfLo; lHi *= sfHi;

        // ---- P = exp(S - m), rescale O, row sums ----
        float rsLo = 0.f, rsHi = 0.f;
#pragma unroll
        for (int ni = 0; ni < 16; ni++) {
            const float p0 = __expf(sacc[ni][0] - mNewLo);
            const float p1 = __expf(sacc[ni][1] - mNewLo);
            const float p2 = __expf(sacc[ni][2] - mNewHi);
            const float p3 = __expf(sacc[ni][3] - mNewHi);
            rsLo += p0 + p1; rsHi += p2 + p3;
            sacc[ni][0] = p0; sacc[ni][1] = p1; sacc[ni][2] = p2; sacc[ni][3] = p3;
            oacc[ni][0] *= sfLo; oacc[ni][1] *= sfLo;
            oacc[ni][2] *= sfHi; oacc[ni][3] *= sfHi;
        }
        rsLo += __shfl_xor_sync(0xffffffffu, rsLo, 1);
        rsLo += __shfl_xor_sync(0xffffffffu, rsLo, 2);
        rsHi += __shfl_xor_sync(0xffffffffu, rsHi, 1);
        rsHi += __shfl_xor_sync(0xffffffffu, rsHi, 2);
        lLo += rsLo; lHi += rsHi;

        // ---- O += P @ V ----
#pragma unroll
        for (int ks = 0; ks < 8; ks++) {
            unsigned af[4];
            {
                __half2 h0 = __floats2half2_rn(sacc[2 * ks][0], sacc[2 * ks][1]);
                __half2 h1 = __floats2half2_rn(sacc[2 * ks][2], sacc[2 * ks][3]);
                __half2 h2 = __floats2half2_rn(sacc[2 * ks + 1][0], sacc[2 * ks + 1][1]);
                __half2 h3 = __floats2half2_rn(sacc[2 * ks + 1][2], sacc[2 * ks + 1][3]);
                af[0] = *(unsigned*)&h0; af[1] = *(unsigned*)&h1;
                af[2] = *(unsigned*)&h2; af[3] = *(unsigned*)&h3;
            }
#pragma unroll
            for (int nb = 0; nb < 8; nb++) {
                unsigned vf[4];
                unsigned adr = smemS + FA_V_OFF(buf) +
                    (unsigned)(((ks * 16 + bLR) * FA_PITCH + nb * 16 + bLC) << 1);
                LDSM4T(vf, adr);
                MMA16816(oacc[2 * nb],     af, vf[0], vf[1]);
                MMA16816(oacc[2 * nb + 1], af, vf[2], vf[3]);
            }
        }
        __syncthreads();
    }

    // ---- epilogue: normalize + write fp16 ----
    const float invLo = 1.f / lLo, invHi = 1.f / lHi;
    __half* pO = O + chunk + (long long)(qt * 128 + w * 16) * HD_;
#pragma unroll
    for (int ni = 0; ni < 16; ni++) {
        const int c = ni * 8 + (lane & 3) * 2;
        __half2 vlo = __floats2half2_rn(oacc[ni][0] * invLo, oacc[ni][1] * invLo);
        __half2 vhi = __floats2half2_rn(oacc[ni][2] * invHi, oacc[ni][3] * invHi);
        *(__half2*)&pO[(long long)(lane >> 2) * HD_ + c] = vlo;
        *(__half2*)&pO[(long long)((lane >> 2) + 8) * HD_ + c] = vhi;
    }
}

// ---------------- batched fp32 -> fp16 convert (up to 4 tensors) -----------
__global__ __launch_bounds__(256)
void conv4_kernel(const float* __restrict__ s0, const float* __restrict__ s1,
                  const float* __restrict__ s2, const float* __restrict__ s3,
                  __half* __restrict__ o0, __half* __restrict__ o1,
                  __half* __restrict__ o2, __half* __restrict__ o3,
                  long long n0, long long n1, long long n2, long long n3)
{
    long long i = ((long long)blockIdx.x * 256 + threadIdx.x) * 8;
    const float* s; __half* o;
    if (i < n0)                     { s = s0; o = o0; }
    else if ((i -= n0) < n1)        { s = s1; o = o1; }
    else if ((i -= n1) < n2)        { s = s2; o = o2; }
    else if ((i -= n2) < n3)        { s = s3; o = o3; }
    else return;
    float4 v0 = *(const float4*)(s + i);
    float4 v1 = *(const float4*)(s + i + 4);
    __half2 r[4];
    r[0].x = __float2half_rn(v0.x); r[0].y = __float2half_rn(v0.y);
    r[1].x = __float2half_rn(v0.z); r[1].y = __float2half_rn(v0.w);
    r[2].x = __float2half_rn(v1.x); r[2].y = __float2half_rn(v1.y);
    r[3].x = __float2half_rn(v1.z); r[3].y = __float2half_rn(v1.w);
    *(uint4*)&o[i] = *(uint4*)r;
}

__global__ __launch_bounds__(256)
void convpack_kernel(const float* __restrict__ s, __half* __restrict__ o,
                     int colOff)
{
    const long long i = ((long long)blockIdx.x * 256 + threadIdx.x) * 8;
    if (i >= (long long)D_ * D_) return;
    const int row = (int)(i >> 10), col = (int)(i & 1023);
    float4 v0 = *(const float4*)(s + i);
    float4 v1 = *(const float4*)(s + i + 4);
    __half2 r[4];
    r[0].x = __float2half_rn(v0.x); r[0].y = __float2half_rn(v0.y);
    r[1].x = __float2half_rn(v0.z); r[1].y = __float2half_rn(v0.w);
    r[2].x = __float2half_rn(v1.x); r[2].y = __float2half_rn(v1.y);
    r[3].x = __float2half_rn(v1.z); r[3].y = __float2half_rn(v1.w);
    *(uint4*)&o[(long long)row * (3 * D_) + colOff + col] = *(uint4*)r;
}

// ---------------- rank-4 relative projections ----------------
__global__ void rproj_kernel(const float* __restrict__ rh,
                             const float* __restrict__ Wrq,
                             const float* __restrict__ Wrk,
                             float* __restrict__ rq, float* __restrict__ rk)
{
    const int i = blockIdx.x * blockDim.x + threadIdx.x;
    if (i >= BL_) return;
    const float h0 = rh[i * 4 + 0], h1v = rh[i * 4 + 1];
    const float h2 = rh[i * 4 + 2], h3 = rh[i * 4 + 3];
#pragma unroll
    for (int r = 0; r < 4; r++) {
        rq[i * 4 + r] = h0 * Wrq[r] + h1v * Wrq[4 + r] + h2 * Wrq[8 + r] + h3 * Wrq[12 + r];
        rk[i * 4 + r] = h0 * Wrk[r] + h1v * Wrk[4 + r] + h2 * Wrk[8 + r] + h3 * Wrk[12 + r];
    }
}

// ---------------- block reduction ----------------
__device__ __forceinline__ float blockReduce(float v, float* red, bool isMax)
{
    __syncthreads();
#pragma unroll
    for (int o = 16; o > 0; o >>= 1) {
        float t = __shfl_xor_sync(0xffffffffu, v, o);
        v = isMax ? fmaxf(v, t) : (v + t);
    }
    const int warp = threadIdx.x >> 5, lane = threadIdx.x & 31;
    if (lane == 0) red[warp] = v;
    __syncthreads();
    if (warp == 0) {
        v = (lane < 8) ? red[lane] : (isMax ? -INFINITY : 0.f);
#pragma unroll
        for (int o = 4; o > 0; o >>= 1) {
            float t = __shfl_xor_sync(0xffffffffu, v, o);
            v = isMax ? fmaxf(v, t) : (v + t);
        }
        if (lane == 0) red[0] = v;
    }
    __syncthreads();
    return red[0];
}

// ---------------- fused residual-add + LayerNorm (+ optional fp16 out) -----
__global__ __launch_bounds__(256)
void add_ln_kernel(const float* __restrict__ x, const float* __restrict__ y,
                   const float* __restrict__ g, const float* __restrict__ be,
                   float* __restrict__ outF, __half* __restrict__ outH)
{
    __shared__ float red[32];
    const long long row = blockIdx.x;
    const float* xp = x + row * D_;
    const float* yp = y + row * D_;
    const int tid = threadIdx.x;

    float v[4];
    float s = 0.f;
#pragma unroll
    for (int j = 0; j < 4; j++) {
        const int i = j * 256 + tid;
        v[j] = xp[i] + yp[i];
        s += v[j];
    }
    const float mean = blockReduce(s, red, false) * (1.f / D_);

    float sq = 0.f;
#pragma unroll
    for (int j = 0; j < 4; j++) {
        const float d = v[j] - mean;
        sq += d * d;
    }
    const float var = blockReduce(sq, red, false) * (1.f / D_);
    const float rstd = rsqrtf(var + LN_EPS);
#pragma unroll
    for (int j = 0; j < 4; j++) {
        const int i = j * 256 + tid;
        const float o = (v[j] - mean) * rstd * g[i] + be[i];
        outF[row * D_ + i] = o;
        if (outH) outH[row * D_ + i] = __float2half_rn(o);
    }
}

// ---------------- host helpers ----------------
#define SMEM_W (STAGES * (128 * APITCH * 2 + BK * (256 + 8) * 2))

static void gemmW(const __half* Ah, const __half* Bh,
                  const float* bias, float* Cf, __half* Ch,
                  int M, int N, int K, int lda, int ldb, int ldc,
                  long long sA, long long sB, long long sC, int batch,
                  float alpha, int doBias, int doRelu,
                  __half* C1 = nullptr, __half* C2 = nullptr, int nSplit = 0)
{
    dim3 grid(N / 256, M / 128, batch), block(256);
    gemm_f16_t<128, 256, 2, 1><<<grid, block, SMEM_W>>>(Ah, Bh, bias, Cf, Ch, C1, C2,
                                                        K, lda, ldb, ldc, sA, sB, sC,
                                                        alpha, doBias, doRelu, nSplit);
}

template <typename T>
static T* sym(T* symbol) { void* p; cudaGetSymbolAddress(&p, (const void*)symbol); return (T*)p; }

extern "C" void kernel_launch(void* const* d_in, const int* in_sizes, int n_in,
                              void* d_out, int out_size)
{
    const float* h   = (const float*)d_in[0];
    const float* rh  = (const float*)d_in[1];
    const float* Wq  = (const float*)d_in[2];
    const float* Wk  = (const float*)d_in[3];
    const float* Wv  = (const float*)d_in[4];
    const float* Wo  = (const float*)d_in[5];
    const float* Wrk = (const float*)d_in[6];
    const float* Wrq = (const float*)d_in[7];
    const float* W1  = (const float*)d_in[8];
    const float* b1  = (const float*)d_in[9];
    const float* W2  = (const float*)d_in[10];
    const float* b2  = (const float*)d_in[11];
    const float* g1  = (const float*)d_in[12];
    const float* be1 = (const float*)d_in[13];
    const float* g2  = (const float*)d_in[14];
    const float* be2 = (const float*)d_in[15];
    float* out = (float*)d_out;

    cudaFuncSetAttribute((const void*)gemm_f16_t<128, 256, 2, 1>,
                         cudaFuncAttributeMaxDynamicSharedMemorySize, SMEM_W);
    cudaFuncSetAttribute((const void*)flash_attn_kernel,
                         cudaFuncAttributeMaxDynamicSharedMemorySize, FA_SMEM);

    __half *hh = sym(g_hh), *Wqkv = sym(g_Wqkv);
    __half *Woh = sym(g_Woh), *W1h = sym(g_W1h), *W2h = sym(g_W2h);
    __half *qh = sym(g_qh), *kh = sym(g_kh), *vh = sym(g_vh);
    __half *ch = sym(g_ch), *h1h = sym(g_h1h), *fh = sym(g_fh);
    float *hsa = sym(g_hsa), *h1 = sym(g_h1), *hf = sym(g_hf);
    float *rq = sym(g_rq), *rk = sym(g_rk);

    const long long nH = (long long)BL_ * D_;
    const long long nW = (long long)D_ * D_;
    const long long nF = (long long)D_ * FFN_;
    const int cgrid = (int)(nW / 2048);

    // converts: h + packed QKV weights
    conv4_kernel<<<(int)(nH / 2048), 256>>>(h, nullptr, nullptr, nullptr,
                                            hh, nullptr, nullptr, nullptr, nH, 0, 0, 0);
    convpack_kernel<<<cgrid, 256>>>(Wq, Wqkv, 0);
    convpack_kernel<<<cgrid, 256>>>(Wk, Wqkv, D_);
    convpack_kernel<<<cgrid, 256>>>(Wv, Wqkv, 2 * D_);
    // fused QKV projection
    gemmW(hh, Wqkv, nullptr, nullptr, qh, BL_, 3 * D_, D_, D_, 3 * D_, D_,
          0, 0, 0, 1, 1.f, 0, 0, kh, vh, 1);
    // rank-4 projections
    rproj_kernel<<<BL_ / 256, 256>>>(rh, Wrq, Wrk, rq, rk);
    // fused flash attention -> ctx fp16
    {
        dim3 grid(16, 1, B_ * NH_);
        flash_attn_kernel<<<grid, 256, FA_SMEM>>>(qh, kh, vh, rq, rk, ch);
    }
    // convert Wo, W1, W2
    conv4_kernel<<<(int)((nW + 2 * nF) / 2048), 256>>>(
        Wo, W1, W2, nullptr, Woh, W1h, W2h, nullptr, nW, nF, nF, 0);
    // output projection
    gemmW(ch, Woh, nullptr, hsa, nullptr, BL_, D_, D_, D_, D_, D_, 0, 0, 0, 1, 1.f, 0, 0);
    // h1 = LN(hsa + h)
    add_ln_kernel<<<BL_, 256>>>(hsa, h, g1, be1, h1, h1h);
    // FFN up
    gemmW(h1h, W1h, b1, nullptr, fh, BL_, FFN_, D_, D_, FFN_, FFN_, 0, 0, 0, 1, 1.f, 1, 1);
    // FFN down
    gemmW(fh, W2h, b2, hf, nullptr, BL_, D_, FFN_, FFN_, D_, D_, 0, 0, 0, 1, 1.f, 1, 0);
    // h2 = LN(h1 + hf) -> out
    add_ln_kernel<<<BL_, 256>>>(h1, hf, g2, be2, out, nullptr);
}